// round 3
// baseline (speedup 1.0000x reference)
#include <cuda_runtime.h>
#include <math.h>

// Problem constants
#define B_   16
#define S_   64
#define N_   100
#define H_   256
#define BN_  1600
#define NBLK 134     // 134 blocks x 12 rows = 1608 >= 1600
#define MBR  12      // rows per block (even -> clean f32x2 pairing)
#define RH   6       // rows per thread-half
#define NT   512     // threads per block

typedef unsigned long long ull;

// ---------------------------------------------------------------------------
// Repacked weights (device globals; filled by prep_kernel every launch).
// g_W0/g_W1: [512 k][256 unit] float4 {wi,wf,wg,wo}. k<256 -> W_ih, k>=256 -> W_hh.
// g_B0/g_B1: [256] float4 combined bias {bi,bf,bg,bo}.
// g_HW: [256 k][512 u] packed head layer-1 (cen 0..127, svd 128..255, lsvd 256..511)
// ---------------------------------------------------------------------------
__device__ float4 g_W0[512 * 256];
__device__ float4 g_W1[512 * 256];
__device__ float4 g_B0[256];
__device__ float4 g_B1[256];
__device__ float  g_HW[256 * 512];
__device__ float  g_HB[512];

__global__ void prep_kernel(
    const float* __restrict__ Wih0, const float* __restrict__ Whh0,
    const float* __restrict__ bih0, const float* __restrict__ bhh0,
    const float* __restrict__ Wih1, const float* __restrict__ Whh1,
    const float* __restrict__ bih1, const float* __restrict__ bhh1,
    const float* __restrict__ cw1,  const float* __restrict__ cb1,
    const float* __restrict__ sw1,  const float* __restrict__ sb1,
    const float* __restrict__ lw1,  const float* __restrict__ lb1)
{
    int idx = blockIdx.x * blockDim.x + threadIdx.x;
    int stride = gridDim.x * blockDim.x;

    // LSTM weights: transpose + gate-interleave
    for (int i = idx; i < 512 * 256; i += stride) {
        int k = i >> 8, j = i & 255;
        int kk = k & 255;
        const float* s0 = (k < 256) ? Wih0 : Whh0;
        const float* s1 = (k < 256) ? Wih1 : Whh1;
        float4 v0, v1;
        v0.x = s0[(0 * 256 + j) * 256 + kk];
        v0.y = s0[(1 * 256 + j) * 256 + kk];
        v0.z = s0[(2 * 256 + j) * 256 + kk];
        v0.w = s0[(3 * 256 + j) * 256 + kk];
        v1.x = s1[(0 * 256 + j) * 256 + kk];
        v1.y = s1[(1 * 256 + j) * 256 + kk];
        v1.z = s1[(2 * 256 + j) * 256 + kk];
        v1.w = s1[(3 * 256 + j) * 256 + kk];
        g_W0[i] = v0;
        g_W1[i] = v1;
    }

    // Head layer-1 packed transpose
    for (int i = idx; i < 256 * 512; i += stride) {
        int k = i >> 9, u = i & 511;
        float v;
        if (u < 128)      v = cw1[u * 256 + k];
        else if (u < 256) v = sw1[(u - 128) * 256 + k];
        else              v = lw1[(u - 256) * 256 + k];
        g_HW[i] = v;
    }

    if (idx < 256) {
        float4 b0, b1;
        b0.x = bih0[idx]       + bhh0[idx];
        b0.y = bih0[256 + idx] + bhh0[256 + idx];
        b0.z = bih0[512 + idx] + bhh0[512 + idx];
        b0.w = bih0[768 + idx] + bhh0[768 + idx];
        b1.x = bih1[idx]       + bhh1[idx];
        b1.y = bih1[256 + idx] + bhh1[256 + idx];
        b1.z = bih1[512 + idx] + bhh1[512 + idx];
        b1.w = bih1[768 + idx] + bhh1[768 + idx];
        g_B0[idx] = b0;
        g_B1[idx] = b1;
    }
    if (idx < 512) {
        g_HB[idx] = (idx < 128) ? cb1[idx]
                  : (idx < 256) ? sb1[idx - 128]
                                : lb1[idx - 256];
    }
}

// ---------------------------------------------------------------------------
// f32x2 helpers
// ---------------------------------------------------------------------------
__device__ __forceinline__ ull fma2(ull a, ull b, ull c) {
    ull d;
    asm("fma.rn.f32x2 %0, %1, %2, %3;" : "=l"(d) : "l"(a), "l"(b), "l"(c));
    return d;
}
__device__ __forceinline__ ull pack2(float x, float y) {
    ull d; asm("mov.b64 %0, {%1, %2};" : "=l"(d) : "f"(x), "f"(y)); return d;
}
__device__ __forceinline__ float2 unpack2(ull v) {
    float2 r; asm("mov.b64 {%0, %1}, %2;" : "=f"(r.x), "=f"(r.y) : "l"(v)); return r;
}
__device__ __forceinline__ float sigf(float x) { return 1.f / (1.f + expf(-x)); }

// ---------------------------------------------------------------------------
// Activation smem layout: dup-packed float4 per (k2, row):
//   A[k2*MBR + r] = {a_{2k2}, a_{2k2}, a_{2k2+1}, a_{2k2+1}}   (k2 in 0..127)
// so one LDS.128 gives {a,a} b64 operands for two consecutive k.
// ---------------------------------------------------------------------------

// One LSTM cell for this thread's RH rows. Thread owns hidden unit u for
// rows [roff, roff+RH). A: input [128][MBR] dup-packed. Hs: h state (same
// layout), read then overwritten. C: per-thread cell state regs.
__device__ __forceinline__ void lstm_cell2(
    const float4* __restrict__ W, const float4* __restrict__ Bv,
    const float* __restrict__ A, float* __restrict__ Hs,
    float* C, int u, int roff)
{
    const ulonglong2* Wa = ((const ulonglong2*)W) + u;             // k < 256 (input)
    const ulonglong2* Wh = ((const ulonglong2*)W) + 256 * 256 + u; // k >= 256 (hidden)
    const ulonglong2* A2 = ((const ulonglong2*)A) + roff;
    const ulonglong2* H2 = ((const ulonglong2*)Hs) + roff;

    ulonglong2 b = ((const ulonglong2*)Bv)[u];
    ull aIF[RH], aGO[RH];
#pragma unroll
    for (int j = 0; j < RH; j++) { aIF[j] = b.x; aGO[j] = b.y; }

#pragma unroll 2
    for (int k2 = 0; k2 < 128; k2++) {
        ulonglong2 wa0 = Wa[(2 * k2 + 0) * 256];
        ulonglong2 wa1 = Wa[(2 * k2 + 1) * 256];
        ulonglong2 wh0 = Wh[(2 * k2 + 0) * 256];
        ulonglong2 wh1 = Wh[(2 * k2 + 1) * 256];
#pragma unroll
        for (int j = 0; j < RH; j++) {
            ulonglong2 av = A2[k2 * MBR + j];   // {a_k,a_k},{a_k1,a_k1}
            ulonglong2 hv = H2[k2 * MBR + j];
            aIF[j] = fma2(av.x, wa0.x, aIF[j]);
            aGO[j] = fma2(av.x, wa0.y, aGO[j]);
            aIF[j] = fma2(av.y, wa1.x, aIF[j]);
            aGO[j] = fma2(av.y, wa1.y, aGO[j]);
            aIF[j] = fma2(hv.x, wh0.x, aIF[j]);
            aGO[j] = fma2(hv.x, wh0.y, aGO[j]);
            aIF[j] = fma2(hv.y, wh1.x, aIF[j]);
            aGO[j] = fma2(hv.y, wh1.y, aGO[j]);
        }
    }
    __syncthreads();  // all reads of Hs done before overwrite
#pragma unroll
    for (int j = 0; j < RH; j++) {
        float2 gif = unpack2(aIF[j]);
        float2 ggo = unpack2(aGO[j]);
        float iv = sigf(gif.x);
        float fv = sigf(gif.y);
        float gv = tanhf(ggo.x);
        float ov = sigf(ggo.y);
        float c = fv * C[j] + iv * gv;
        C[j] = c;
        float h = ov * tanhf(c);
        // dup-store {h,h} into Hs at k2 = u>>1, half = u&1
        ((ull*)Hs)[((u >> 1) * MBR + roff + j) * 2 + (u & 1)] = pack2(h, h);
    }
    __syncthreads();
}

// LayerNorm rows of Hs (dup-packed) into OV (dup-packed). Warp w < MBR does row w.
__device__ __forceinline__ void layer_norm2(
    const float* __restrict__ Hs, float* __restrict__ OV,
    const float* __restrict__ LNG, const float* __restrict__ LNB, int tid)
{
    int w = tid >> 5, lane = tid & 31;
    if (w < MBR) {
        int r = w;
        float v[8];
        float s = 0.f, sq = 0.f;
#pragma unroll
        for (int q = 0; q < 8; q++) {
            int i = lane + 32 * q;
            v[q] = Hs[((i >> 1) * MBR + r) * 4 + (i & 1) * 2];
            s += v[q];
            sq += v[q] * v[q];
        }
#pragma unroll
        for (int off = 16; off > 0; off >>= 1) {
            s  += __shfl_xor_sync(0xffffffffu, s, off);
            sq += __shfl_xor_sync(0xffffffffu, sq, off);
        }
        float m = s * (1.f / 256.f);
        float var = sq * (1.f / 256.f) - m * m;
        float inv = rsqrtf(var + 1e-5f);
#pragma unroll
        for (int q = 0; q < 8; q++) {
            int i = lane + 32 * q;
            float o = (v[q] - m) * inv * LNG[i] + LNB[i];
            ((ull*)OV)[((i >> 1) * MBR + r) * 2 + (i & 1)] = pack2(o, o);
        }
    }
    __syncthreads();
}

__global__ void __launch_bounds__(NT, 1) lstm_main(
    const float* __restrict__ x,
    const float* __restrict__ ln_g, const float* __restrict__ ln_b,
    const float* __restrict__ cw2,  const float* __restrict__ cb2,
    const float* __restrict__ sw2,  const float* __restrict__ sb2,
    const float* __restrict__ lw2,  const float* __restrict__ lb2,
    float* __restrict__ out, int steps)
{
    extern __shared__ float sm[];
    float* IV  = sm;                   // [128][MBR] float4 dup-packed = 6144 floats
    float* H0  = IV + 128 * MBR * 4;
    float* H1  = H0 + 128 * MBR * 4;
    float* HID = H1 + 128 * MBR * 4;   // [MBR][512] head hidden (plain)
    float* LNG = HID + MBR * 512;      // [256]
    float* LNB = LNG + 256;            // [256]

    int tid = threadIdx.x, bid = blockIdx.x;
    int u = tid & 255;          // hidden unit owned
    int roff = (tid >> 8) * RH; // row offset for this half

    float C0[RH], C1[RH];
#pragma unroll
    for (int j = 0; j < RH; j++) {
        C0[j] = 0.f; C1[j] = 0.f;
        ((ull*)H0)[((u >> 1) * MBR + roff + j) * 2 + (u & 1)] = 0ull;
        ((ull*)H1)[((u >> 1) * MBR + roff + j) * 2 + (u & 1)] = 0ull;
    }
    if (tid < 256) { LNG[tid] = ln_g[tid]; LNB[tid] = ln_b[tid]; }
    __syncthreads();

    // -------- encoder --------
    for (int t = 0; t < S_; t++) {
#pragma unroll
        for (int j = 0; j < RH; j++) {
            int s = bid + NBLK * (roff + j);
            float v = 0.f;
            if (s < BN_) {
                int b = s / N_, n = s % N_;
                v = x[(b * (S_ * N_) + t * N_ + n) * H_ + u];
            }
            ((ull*)IV)[((u >> 1) * MBR + roff + j) * 2 + (u & 1)] = pack2(v, v);
        }
        __syncthreads();
        lstm_cell2(g_W0, g_B0, IV, H0, C0, u, roff);
        lstm_cell2(g_W1, g_B1, H0, H1, C1, u, roff);
    }
    layer_norm2(H1, IV, LNG, LNB, tid);

    // -------- decoder --------
    const float4* IV4 = (const float4*)IV;
    for (int td = 0; td < steps; td++) {
        // heads layer 1: thread owns head unit hu = tid (512 units), all MBR rows
        {
            int hu = tid;
            float a[MBR];
            float hb = g_HB[hu];
#pragma unroll
            for (int r = 0; r < MBR; r++) a[r] = hb;
            for (int k2 = 0; k2 < 128; k2++) {
                float w0 = g_HW[(2 * k2 + 0) * 512 + hu];
                float w1 = g_HW[(2 * k2 + 1) * 512 + hu];
#pragma unroll
                for (int r = 0; r < MBR; r++) {
                    float4 av = IV4[k2 * MBR + r];  // {a,a,a1,a1}
                    a[r] += w0 * av.x + w1 * av.z;
                }
            }
#pragma unroll
            for (int r = 0; r < MBR; r++)
                HID[r * 512 + hu] = fmaxf(a[r], 0.f);
        }
        __syncthreads();

        // heads layer 2 + output write: MBR*22 = 264 threads, one (row, channel)
        if (tid < MBR * 22) {
            int r = tid / 22, c = tid % 22;
            int s = bid + NBLK * r;
            if (s < BN_) {
                const float* wrow;
                const float* hb;
                int len;
                float acc;
                if (c < 4)      { wrow = cw2 + c * 128;       hb = HID + r * 512;       len = 128; acc = cb2[c]; }
                else if (c < 6) { wrow = sw2 + (c - 4) * 128; hb = HID + r * 512 + 128; len = 128; acc = sb2[c - 4]; }
                else            { wrow = lw2 + (c - 6) * 256; hb = HID + r * 512 + 256; len = 256; acc = lb2[c - 6]; }
                for (int k = 0; k < len; k++) acc += wrow[k] * hb[k];
                int b = s / N_, n = s % N_;
                out[((b * steps + td) * N_ + n) * 22 + c] = acc;
            }
        }

        lstm_cell2(g_W0, g_B0, IV, H0, C0, u, roff);
        lstm_cell2(g_W1, g_B1, H0, H1, C1, u, roff);
        layer_norm2(H1, IV, LNG, LNB, tid);
    }
}

// ---------------------------------------------------------------------------
extern "C" void kernel_launch(void* const* d_in, const int* in_sizes, int n_in,
                              void* d_out, int out_size)
{
    const float* x    = (const float*)d_in[0];
    const float* Wih0 = (const float*)d_in[1];
    const float* Whh0 = (const float*)d_in[2];
    const float* bih0 = (const float*)d_in[3];
    const float* bhh0 = (const float*)d_in[4];
    const float* Wih1 = (const float*)d_in[5];
    const float* Whh1 = (const float*)d_in[6];
    const float* bih1 = (const float*)d_in[7];
    const float* bhh1 = (const float*)d_in[8];
    const float* ln_g = (const float*)d_in[9];
    const float* ln_b = (const float*)d_in[10];
    const float* cw1  = (const float*)d_in[11];
    const float* cb1  = (const float*)d_in[12];
    const float* cw2  = (const float*)d_in[13];
    const float* cb2  = (const float*)d_in[14];
    const float* sw1  = (const float*)d_in[15];
    const float* sb1  = (const float*)d_in[16];
    const float* sw2  = (const float*)d_in[17];
    const float* sb2  = (const float*)d_in[18];
    const float* lw1  = (const float*)d_in[19];
    const float* lb1  = (const float*)d_in[20];
    const float* lw2  = (const float*)d_in[21];
    const float* lb2  = (const float*)d_in[22];
    float* out = (float*)d_out;

    int steps = out_size / (B_ * N_ * 22);  // 35200 elems per decoder step

    prep_kernel<<<128, 256>>>(Wih0, Whh0, bih0, bhh0, Wih1, Whh1, bih1, bhh1,
                              cw1, cb1, sw1, sb1, lw1, lb1);

    const int smem_bytes = (3 * 128 * MBR * 4 + MBR * 512 + 512) * (int)sizeof(float);
    cudaFuncSetAttribute(lstm_main, cudaFuncAttributeMaxDynamicSharedMemorySize, smem_bytes);
    lstm_main<<<NBLK, NT, smem_bytes>>>(x, ln_g, ln_b, cw2, cb2, sw2, sb2,
                                        lw2, lb2, out, steps);
}

// round 4
// speedup vs baseline: 1.6285x; 1.6285x over previous
#include <cuda_runtime.h>
#include <math.h>

// Problem constants
#define B_   16
#define S_   64
#define N_   100
#define H_   256
#define BN_  1600
#define NBLK 134     // 134 blocks x 12 rows = 1608 >= 1600
#define MBR  12      // rows per block (even -> clean f32x2 pairing)
#define RH   6       // rows per thread-half
#define NT   512     // threads per block

typedef unsigned long long ull;

// ---------------------------------------------------------------------------
// Repacked weights (device globals; filled by prep_kernel every launch).
// g_W0/g_W1: [512 k][256 unit] float4 {wi,wf,wg,wo}. k<256 -> W_ih, k>=256 -> W_hh.
// g_B0/g_B1: [256] float4 combined bias {bi,bf,bg,bo}.
// g_HW: [256 k][512 u] packed head layer-1 (cen 0..127, svd 128..255, lsvd 256..511)
// ---------------------------------------------------------------------------
__device__ float4 g_W0[512 * 256];
__device__ float4 g_W1[512 * 256];
__device__ float4 g_B0[256];
__device__ float4 g_B1[256];
__device__ float  g_HW[256 * 512];
__device__ float  g_HB[512];

__global__ void prep_kernel(
    const float* __restrict__ Wih0, const float* __restrict__ Whh0,
    const float* __restrict__ bih0, const float* __restrict__ bhh0,
    const float* __restrict__ Wih1, const float* __restrict__ Whh1,
    const float* __restrict__ bih1, const float* __restrict__ bhh1,
    const float* __restrict__ cw1,  const float* __restrict__ cb1,
    const float* __restrict__ sw1,  const float* __restrict__ sb1,
    const float* __restrict__ lw1,  const float* __restrict__ lb1)
{
    int idx = blockIdx.x * blockDim.x + threadIdx.x;
    int stride = gridDim.x * blockDim.x;

    // LSTM weights: transpose + gate-interleave
    for (int i = idx; i < 512 * 256; i += stride) {
        int k = i >> 8, j = i & 255;
        int kk = k & 255;
        const float* s0 = (k < 256) ? Wih0 : Whh0;
        const float* s1 = (k < 256) ? Wih1 : Whh1;
        float4 v0, v1;
        v0.x = s0[(0 * 256 + j) * 256 + kk];
        v0.y = s0[(1 * 256 + j) * 256 + kk];
        v0.z = s0[(2 * 256 + j) * 256 + kk];
        v0.w = s0[(3 * 256 + j) * 256 + kk];
        v1.x = s1[(0 * 256 + j) * 256 + kk];
        v1.y = s1[(1 * 256 + j) * 256 + kk];
        v1.z = s1[(2 * 256 + j) * 256 + kk];
        v1.w = s1[(3 * 256 + j) * 256 + kk];
        g_W0[i] = v0;
        g_W1[i] = v1;
    }

    // Head layer-1 packed transpose
    for (int i = idx; i < 256 * 512; i += stride) {
        int k = i >> 9, u = i & 511;
        float v;
        if (u < 128)      v = cw1[u * 256 + k];
        else if (u < 256) v = sw1[(u - 128) * 256 + k];
        else              v = lw1[(u - 256) * 256 + k];
        g_HW[i] = v;
    }

    if (idx < 256) {
        float4 b0, b1;
        b0.x = bih0[idx]       + bhh0[idx];
        b0.y = bih0[256 + idx] + bhh0[256 + idx];
        b0.z = bih0[512 + idx] + bhh0[512 + idx];
        b0.w = bih0[768 + idx] + bhh0[768 + idx];
        b1.x = bih1[idx]       + bhh1[idx];
        b1.y = bih1[256 + idx] + bhh1[256 + idx];
        b1.z = bih1[512 + idx] + bhh1[512 + idx];
        b1.w = bih1[768 + idx] + bhh1[768 + idx];
        g_B0[idx] = b0;
        g_B1[idx] = b1;
    }
    if (idx < 512) {
        g_HB[idx] = (idx < 128) ? cb1[idx]
                  : (idx < 256) ? sb1[idx - 128]
                                : lb1[idx - 256];
    }
}

// ---------------------------------------------------------------------------
// f32x2 helpers
// ---------------------------------------------------------------------------
__device__ __forceinline__ ull fma2(ull a, ull b, ull c) {
    ull d;
    asm("fma.rn.f32x2 %0, %1, %2, %3;" : "=l"(d) : "l"(a), "l"(b), "l"(c));
    return d;
}
__device__ __forceinline__ ull pack2(float x, float y) {
    ull d; asm("mov.b64 %0, {%1, %2};" : "=l"(d) : "f"(x), "f"(y)); return d;
}
__device__ __forceinline__ float2 unpack2(ull v) {
    float2 r; asm("mov.b64 {%0, %1}, %2;" : "=f"(r.x), "=f"(r.y) : "l"(v)); return r;
}
__device__ __forceinline__ float sigf(float x) { return 1.f / (1.f + expf(-x)); }

// ---------------------------------------------------------------------------
// Activation smem layout: dup-packed float4 per (k2, row):
//   A[k2*MBR + r] = {a_{2k2}, a_{2k2}, a_{2k2+1}, a_{2k2+1}}   (k2 in 0..127)
// so one LDS.128 gives {a,a} b64 operands for two consecutive k.
// ---------------------------------------------------------------------------

// One LSTM cell for this thread's RH rows. Thread owns hidden unit u for
// rows [roff, roff+RH). A: input [128][MBR] dup-packed. Hs: h state (same
// layout), read then overwritten. C: per-thread cell state regs.
__device__ __forceinline__ void lstm_cell2(
    const float4* __restrict__ W, const float4* __restrict__ Bv,
    const float* __restrict__ A, float* __restrict__ Hs,
    float* C, int u, int roff)
{
    const ulonglong2* Wa = ((const ulonglong2*)W) + u;             // k < 256 (input)
    const ulonglong2* Wh = ((const ulonglong2*)W) + 256 * 256 + u; // k >= 256 (hidden)
    const ulonglong2* A2 = ((const ulonglong2*)A) + roff;
    const ulonglong2* H2 = ((const ulonglong2*)Hs) + roff;

    ulonglong2 b = ((const ulonglong2*)Bv)[u];
    ull aIF[RH], aGO[RH];
#pragma unroll
    for (int j = 0; j < RH; j++) { aIF[j] = b.x; aGO[j] = b.y; }

#pragma unroll 2
    for (int k2 = 0; k2 < 128; k2++) {
        ulonglong2 wa0 = Wa[(2 * k2 + 0) * 256];
        ulonglong2 wa1 = Wa[(2 * k2 + 1) * 256];
        ulonglong2 wh0 = Wh[(2 * k2 + 0) * 256];
        ulonglong2 wh1 = Wh[(2 * k2 + 1) * 256];
#pragma unroll
        for (int j = 0; j < RH; j++) {
            ulonglong2 av = A2[k2 * MBR + j];   // {a_k,a_k},{a_k1,a_k1}
            ulonglong2 hv = H2[k2 * MBR + j];
            aIF[j] = fma2(av.x, wa0.x, aIF[j]);
            aGO[j] = fma2(av.x, wa0.y, aGO[j]);
            aIF[j] = fma2(av.y, wa1.x, aIF[j]);
            aGO[j] = fma2(av.y, wa1.y, aGO[j]);
            aIF[j] = fma2(hv.x, wh0.x, aIF[j]);
            aGO[j] = fma2(hv.x, wh0.y, aGO[j]);
            aIF[j] = fma2(hv.y, wh1.x, aIF[j]);
            aGO[j] = fma2(hv.y, wh1.y, aGO[j]);
        }
    }
    __syncthreads();  // all reads of Hs done before overwrite
#pragma unroll
    for (int j = 0; j < RH; j++) {
        float2 gif = unpack2(aIF[j]);
        float2 ggo = unpack2(aGO[j]);
        float iv = sigf(gif.x);
        float fv = sigf(gif.y);
        float gv = tanhf(ggo.x);
        float ov = sigf(ggo.y);
        float c = fv * C[j] + iv * gv;
        C[j] = c;
        float h = ov * tanhf(c);
        // dup-store {h,h} into Hs at k2 = u>>1, half = u&1
        ((ull*)Hs)[((u >> 1) * MBR + roff + j) * 2 + (u & 1)] = pack2(h, h);
    }
    __syncthreads();
}

// LayerNorm rows of Hs (dup-packed) into OV (dup-packed). Warp w < MBR does row w.
__device__ __forceinline__ void layer_norm2(
    const float* __restrict__ Hs, float* __restrict__ OV,
    const float* __restrict__ LNG, const float* __restrict__ LNB, int tid)
{
    int w = tid >> 5, lane = tid & 31;
    if (w < MBR) {
        int r = w;
        float v[8];
        float s = 0.f, sq = 0.f;
#pragma unroll
        for (int q = 0; q < 8; q++) {
            int i = lane + 32 * q;
            v[q] = Hs[((i >> 1) * MBR + r) * 4 + (i & 1) * 2];
            s += v[q];
            sq += v[q] * v[q];
        }
#pragma unroll
        for (int off = 16; off > 0; off >>= 1) {
            s  += __shfl_xor_sync(0xffffffffu, s, off);
            sq += __shfl_xor_sync(0xffffffffu, sq, off);
        }
        float m = s * (1.f / 256.f);
        float var = sq * (1.f / 256.f) - m * m;
        float inv = rsqrtf(var + 1e-5f);
#pragma unroll
        for (int q = 0; q < 8; q++) {
            int i = lane + 32 * q;
            float o = (v[q] - m) * inv * LNG[i] + LNB[i];
            ((ull*)OV)[((i >> 1) * MBR + r) * 2 + (i & 1)] = pack2(o, o);
        }
    }
    __syncthreads();
}

__global__ void __launch_bounds__(NT, 1) lstm_main(
    const float* __restrict__ x,
    const float* __restrict__ ln_g, const float* __restrict__ ln_b,
    const float* __restrict__ cw2,  const float* __restrict__ cb2,
    const float* __restrict__ sw2,  const float* __restrict__ sb2,
    const float* __restrict__ lw2,  const float* __restrict__ lb2,
    float* __restrict__ out, int steps)
{
    extern __shared__ float sm[];
    float* IV  = sm;                   // [128][MBR] float4 dup-packed = 6144 floats
    float* H0  = IV + 128 * MBR * 4;
    float* H1  = H0 + 128 * MBR * 4;
    float* HID = H1 + 128 * MBR * 4;   // [MBR][512] head hidden (plain)
    float* LNG = HID + MBR * 512;      // [256]
    float* LNB = LNG + 256;            // [256]

    int tid = threadIdx.x, bid = blockIdx.x;
    int u = tid & 255;          // hidden unit owned
    int roff = (tid >> 8) * RH; // row offset for this half

    float C0[RH], C1[RH];
#pragma unroll
    for (int j = 0; j < RH; j++) {
        C0[j] = 0.f; C1[j] = 0.f;
        ((ull*)H0)[((u >> 1) * MBR + roff + j) * 2 + (u & 1)] = 0ull;
        ((ull*)H1)[((u >> 1) * MBR + roff + j) * 2 + (u & 1)] = 0ull;
    }
    if (tid < 256) { LNG[tid] = ln_g[tid]; LNB[tid] = ln_b[tid]; }
    __syncthreads();

    // -------- encoder --------
    for (int t = 0; t < S_; t++) {
#pragma unroll
        for (int j = 0; j < RH; j++) {
            int s = bid + NBLK * (roff + j);
            float v = 0.f;
            if (s < BN_) {
                int b = s / N_, n = s % N_;
                v = x[(b * (S_ * N_) + t * N_ + n) * H_ + u];
            }
            ((ull*)IV)[((u >> 1) * MBR + roff + j) * 2 + (u & 1)] = pack2(v, v);
        }
        __syncthreads();
        lstm_cell2(g_W0, g_B0, IV, H0, C0, u, roff);
        lstm_cell2(g_W1, g_B1, H0, H1, C1, u, roff);
    }
    layer_norm2(H1, IV, LNG, LNB, tid);

    // -------- decoder --------
    const float4* IV4 = (const float4*)IV;
    for (int td = 0; td < steps; td++) {
        // heads layer 1: thread owns head unit hu = tid (512 units), all MBR rows
        {
            int hu = tid;
            float a[MBR];
            float hb = g_HB[hu];
#pragma unroll
            for (int r = 0; r < MBR; r++) a[r] = hb;
            for (int k2 = 0; k2 < 128; k2++) {
                float w0 = g_HW[(2 * k2 + 0) * 512 + hu];
                float w1 = g_HW[(2 * k2 + 1) * 512 + hu];
#pragma unroll
                for (int r = 0; r < MBR; r++) {
                    float4 av = IV4[k2 * MBR + r];  // {a,a,a1,a1}
                    a[r] += w0 * av.x + w1 * av.z;
                }
            }
#pragma unroll
            for (int r = 0; r < MBR; r++)
                HID[r * 512 + hu] = fmaxf(a[r], 0.f);
        }
        __syncthreads();

        // heads layer 2 + output write: MBR*22 = 264 threads, one (row, channel)
        if (tid < MBR * 22) {
            int r = tid / 22, c = tid % 22;
            int s = bid + NBLK * r;
            if (s < BN_) {
                const float* wrow;
                const float* hb;
                int len;
                float acc;
                if (c < 4)      { wrow = cw2 + c * 128;       hb = HID + r * 512;       len = 128; acc = cb2[c]; }
                else if (c < 6) { wrow = sw2 + (c - 4) * 128; hb = HID + r * 512 + 128; len = 128; acc = sb2[c - 4]; }
                else            { wrow = lw2 + (c - 6) * 256; hb = HID + r * 512 + 256; len = 256; acc = lb2[c - 6]; }
                for (int k = 0; k < len; k++) acc += wrow[k] * hb[k];
                int b = s / N_, n = s % N_;
                out[((b * steps + td) * N_ + n) * 22 + c] = acc;
            }
        }

        lstm_cell2(g_W0, g_B0, IV, H0, C0, u, roff);
        lstm_cell2(g_W1, g_B1, H0, H1, C1, u, roff);
        layer_norm2(H1, IV, LNG, LNB, tid);
    }
}

// ---------------------------------------------------------------------------
extern "C" void kernel_launch(void* const* d_in, const int* in_sizes, int n_in,
                              void* d_out, int out_size)
{
    const float* x    = (const float*)d_in[0];
    const float* Wih0 = (const float*)d_in[1];
    const float* Whh0 = (const float*)d_in[2];
    const float* bih0 = (const float*)d_in[3];
    const float* bhh0 = (const float*)d_in[4];
    const float* Wih1 = (const float*)d_in[5];
    const float* Whh1 = (const float*)d_in[6];
    const float* bih1 = (const float*)d_in[7];
    const float* bhh1 = (const float*)d_in[8];
    const float* ln_g = (const float*)d_in[9];
    const float* ln_b = (const float*)d_in[10];
    const float* cw1  = (const float*)d_in[11];
    const float* cb1  = (const float*)d_in[12];
    const float* cw2  = (const float*)d_in[13];
    const float* cb2  = (const float*)d_in[14];
    const float* sw1  = (const float*)d_in[15];
    const float* sb1  = (const float*)d_in[16];
    const float* sw2  = (const float*)d_in[17];
    const float* sb2  = (const float*)d_in[18];
    const float* lw1  = (const float*)d_in[19];
    const float* lb1  = (const float*)d_in[20];
    const float* lw2  = (const float*)d_in[21];
    const float* lb2  = (const float*)d_in[22];
    float* out = (float*)d_out;

    int steps = out_size / (B_ * N_ * 22);  // 35200 elems per decoder step

    prep_kernel<<<128, 256>>>(Wih0, Whh0, bih0, bhh0, Wih1, Whh1, bih1, bhh1,
                              cw1, cb1, sw1, sb1, lw1, lb1);

    const int smem_bytes = (3 * 128 * MBR * 4 + MBR * 512 + 512) * (int)sizeof(float);
    cudaFuncSetAttribute(lstm_main, cudaFuncAttributeMaxDynamicSharedMemorySize, smem_bytes);
    lstm_main<<<NBLK, NT, smem_bytes>>>(x, ln_g, ln_b, cw2, cb2, sw2, sb2,
                                        lw2, lb2, out, steps);
}